// round 12
// baseline (speedup 1.0000x reference)
#include <cuda_runtime.h>
#include <cuda_fp16.h>
#include <stdint.h>

// Problem constants
constexpr int BB = 128;    // batch
constexpr int TT = 512;    // seq len
constexpr int EE = 256;    // embed
constexpr int HH = 512;    // hidden
constexpr int GG = 2048;   // 4*H gates
constexpr int MR = BB * TT;  // 65536 rows

constexpr int NGROUP = 8;   // batch groups
constexpr int NSLICE = 16;  // CTAs per group
constexpr int BSUB   = 16;  // batch rows per group

// ---------------- static device scratch (allocation-free) ----------------
__device__ __half g_x16[(size_t)MR * EE];
__device__ __half g_h1 [(size_t)MR * HH];
__device__ __half g_xg [(size_t)MR * GG];     // fp16 xg, layer-2 only
__device__ __half g_wih0p[GG * EE];
__device__ __half g_wih1p[GG * HH];
__device__ __half g_whh0p[GG * HH];
__device__ __half g_whh1p[GG * HH];
__device__ float  g_bias0[GG];
__device__ float  g_bias1[GG];
// h exchange, per-peer contiguous: [parity][group][peer][row16][32 halves]
__device__ __half g_hbuf[2 * NGROUP * NSLICE * BSUB * 32];
__device__ float  g_hlast[BB * HH];
__device__ int    g_flag[NGROUP * NSLICE * 32]; // 128B-spread barrier flags

// Column permutation: new index m -> original gate column n
// m = c*128 + u*4 + q  (c = CTA slice 0..15, u = hidden-in-slice 0..31, q = gate 0..3)
// n = q*512 + c*32 + u
__device__ __forceinline__ int perm_orig(int m) {
    int cc = m >> 7, l = m & 127, u = l >> 2, q = l & 3;
    return q * 512 + cc * 32 + u;
}

// ---------------- prep kernels ----------------
__global__ void k_conv_x(const float* __restrict__ x) {
    size_t i = (size_t)blockIdx.x * blockDim.x + threadIdx.x;
    if (i < (size_t)MR * EE) g_x16[i] = __float2half(x[i]);
}

__global__ void k_prep_w(const float* __restrict__ wih0, const float* __restrict__ whh0,
                         const float* __restrict__ wih1, const float* __restrict__ whh1) {
    int which = blockIdx.y;
    size_t i = (size_t)blockIdx.x * blockDim.x + threadIdx.x;
    const float* src; __half* dst; int K;
    if      (which == 0) { src = wih0; dst = g_wih0p; K = EE; }
    else if (which == 1) { src = whh0; dst = g_whh0p; K = HH; }
    else if (which == 2) { src = wih1; dst = g_wih1p; K = HH; }
    else                 { src = whh1; dst = g_whh1p; K = HH; }
    if (i >= (size_t)GG * K) return;
    int m = (int)(i / K), k = (int)(i % K);
    int n = perm_orig(m);
    dst[i] = __float2half(src[(size_t)n * K + k]);
}

__global__ void k_prep_b(const float* __restrict__ bih0, const float* __restrict__ bhh0,
                         const float* __restrict__ bih1, const float* __restrict__ bhh1) {
    int m = blockIdx.x * blockDim.x + threadIdx.x;
    if (m >= GG) return;
    int n = perm_orig(m);
    if (blockIdx.y == 0) g_bias0[m] = bih0[n] + bhh0[n];
    else                 g_bias1[m] = bih1[n] + bhh1[n];
}

__global__ void k_reset() {
    int i = blockIdx.x * blockDim.x + threadIdx.x;
    if (i < 2 * BB * HH / 2) ((uint32_t*)g_hbuf)[i] = 0u;
    if (i < NGROUP * NSLICE * 32) g_flag[i] = 0;
}

// ---------------- asm helpers ----------------
__device__ __forceinline__ void mma16816(float* d, const uint32_t* a, uint32_t b0, uint32_t b1) {
    asm volatile(
        "mma.sync.aligned.m16n8k16.row.col.f32.f16.f16.f32 "
        "{%0,%1,%2,%3},{%4,%5,%6,%7},{%8,%9},{%0,%1,%2,%3};"
        : "+f"(d[0]), "+f"(d[1]), "+f"(d[2]), "+f"(d[3])
        : "r"(a[0]), "r"(a[1]), "r"(a[2]), "r"(a[3]), "r"(b0), "r"(b1));
}

__device__ __forceinline__ void ldsm4(uint32_t& r0, uint32_t& r1, uint32_t& r2, uint32_t& r3,
                                      uint32_t addr) {
    asm volatile("ldmatrix.sync.aligned.m8n8.x4.shared.b16 {%0,%1,%2,%3}, [%4];"
                 : "=r"(r0), "=r"(r1), "=r"(r2), "=r"(r3) : "r"(addr));
}

__device__ __forceinline__ void cp16(uint32_t dst, const void* src) {
    asm volatile("cp.async.cg.shared.global [%0], [%1], 16;" :: "r"(dst), "l"(src));
}
__device__ __forceinline__ void cp_commit() { asm volatile("cp.async.commit_group;"); }

__device__ __forceinline__ float tanhfast(float x) {
    float y;
    asm("tanh.approx.f32 %0, %1;" : "=f"(y) : "f"(x));
    return y;
}
__device__ __forceinline__ float sigm(float x) {
    return fmaf(0.5f, tanhfast(0.5f * x), 0.5f);
}

// ---------------- xg GEMM (layer 2 only): C[M,2048] = h1[M,512] @ W^T + bias ------------
// BM=128, BN=128, BK=32, 256 threads (8 warps: 4 M x 2 N, warp tile 32x64)
// 4-stage cp.async ring, loop-split tail waits; smem-staged coalesced epilogue.
constexpr int GEMM_STAGE = (128 + 128) * 40;           // halves per stage
constexpr int GEMM_SMEM  = 4 * GEMM_STAGE * 2;         // 81920 B

template <int K>
__global__ __launch_bounds__(256, 2) void k_gemm_xg() {
    const __half* __restrict__ A = g_h1;
    const __half* __restrict__ W = g_wih1p;
    const float*  __restrict__ bias = g_bias1;

    extern __shared__ __align__(16) __half gsm[];

    int tid = threadIdx.x;
    int m0 = blockIdx.y * 128;
    int n0 = blockIdx.x * 128;
    int lane = tid & 31, warp = tid >> 5;
    int wm = warp & 3, wn = warp >> 2;
    int r = lane >> 2, tg = lane & 3;

    uint32_t gsmu = (uint32_t)__cvta_generic_to_shared(gsm);
    const uint32_t stageB = GEMM_STAGE * 2;

    uint32_t laneA = (uint32_t)(((lane & 15) * 40 + ((lane >> 4) << 3)) << 1);
    int bnn = wn * 64 + ((lane >> 4) & 1) * 8 + (lane & 7);
    uint32_t laneB = (uint32_t)((bnn * 40 + ((lane >> 3) & 1) * 8) << 1);

    float acc[2][8][4] = {};
    constexpr int KT = K / 32;

    auto load_stage = [&](int st, int kt) {
        uint32_t base = gsmu + st * stageB;
#pragma unroll
        for (int i = 0; i < 2; i++) {
            int chunk = tid + i * 256;
            int row = chunk >> 2, c4 = chunk & 3;
            cp16(base + (uint32_t)((row * 40 + c4 * 8) * 2),
                 A + (size_t)(m0 + row) * K + kt * 32 + c4 * 8);
        }
#pragma unroll
        for (int i = 0; i < 2; i++) {
            int chunk = tid + i * 256;
            int row = chunk >> 2, c4 = chunk & 3;
            cp16(base + (uint32_t)(128 * 80) + (uint32_t)((row * 40 + c4 * 8) * 2),
                 W + (size_t)(n0 + row) * K + kt * 32 + c4 * 8);
        }
        cp_commit();
    };

    auto consume = [&](int st) {
        uint32_t abase = gsmu + st * stageB;
        uint32_t bbase = abase + (uint32_t)(128 * 80);
#pragma unroll
        for (int kk = 0; kk < 2; kk++) {
            uint32_t kko = (uint32_t)(kk * 32);
            uint32_t a[2][4];
#pragma unroll
            for (int mt = 0; mt < 2; mt++) {
                uint32_t addr = abase + (uint32_t)(((wm * 32 + mt * 16) * 40) << 1) + laneA + kko;
                ldsm4(a[mt][0], a[mt][1], a[mt][2], a[mt][3], addr);
            }
            uint32_t p[4][4];
#pragma unroll
            for (int q = 0; q < 4; q++)
                ldsm4(p[q][0], p[q][1], p[q][2], p[q][3],
                      bbase + laneB + (uint32_t)(q * 16 * 80) + kko);
#pragma unroll
            for (int mt = 0; mt < 2; mt++)
#pragma unroll
                for (int q = 0; q < 4; q++) {
                    mma16816(acc[mt][2 * q],     a[mt], p[q][0], p[q][1]);
                    mma16816(acc[mt][2 * q + 1], a[mt], p[q][2], p[q][3]);
                }
        }
    };

    load_stage(0, 0);
    load_stage(1, 1);
    load_stage(2, 2);

    int st = 0;
#pragma unroll 1
    for (int kt = 0; kt < KT - 3; kt++) {
        asm volatile("cp.async.wait_group 2;");
        __syncthreads();
        load_stage((st + 3) & 3, kt + 3);
        consume(st);
        st = (st + 1) & 3;
    }
    asm volatile("cp.async.wait_group 2;");
    __syncthreads();
    consume(st); st = (st + 1) & 3;
    asm volatile("cp.async.wait_group 1;");
    __syncthreads();
    consume(st); st = (st + 1) & 3;
    asm volatile("cp.async.wait_group 0;");
    __syncthreads();
    consume(st);

    // epilogue: bias add, stage in smem (stride 136 halves, conflict-free),
    // then fully-coalesced uint4 streaming stores.
    __syncthreads();   // stage buffers now free
    __half* sC = gsm;  // [128][136]
#pragma unroll
    for (int mt = 0; mt < 2; mt++)
#pragma unroll
        for (int j = 0; j < 8; j++) {
            int m = wm * 32 + mt * 16 + r;
            int n = wn * 64 + (j >> 1) * 16 + (j & 1) * 8 + tg * 2;
            float b0 = bias[n0 + n], b1 = bias[n0 + n + 1];
            *(__half2*)&sC[m * 136 + n] =
                __floats2half2_rn(acc[mt][j][0] + b0, acc[mt][j][1] + b1);
            *(__half2*)&sC[(m + 8) * 136 + n] =
                __floats2half2_rn(acc[mt][j][2] + b0, acc[mt][j][3] + b1);
        }
    __syncthreads();
#pragma unroll
    for (int i = 0; i < 8; i++) {
        int ch = tid + i * 256;            // 2048 chunks of 16B
        int row = ch >> 4, off = ch & 15;
        uint4 v = *(uint4*)&sC[row * 136 + off * 8];
        *(uint4*)&g_xg[(size_t)(m0 + row) * GG + n0 + off * 8] = v;
    }
}

// ---------------- persistent LSTM recurrence ----------------
// 128 CTAs = 8 groups x 16 slices, 256 threads (8 warps, 16 gate cols/warp).
// CTA (g,c): batch rows [g*16,g*16+16), hidden [c*32,c*32+32), permuted gate
// cols [c*128,c*128+128). W_hh fragments in REGISTERS (128/thread).
// Activations are REGISTER-RESIDENT: warp w owns all 4 gates of hidden units
// w*4..w*4+3, so a 2x shfl.xor(1) pair exchange gives each lane the full
// (i,f,g,o) of one (row, hidden) cell — no smem gate scatter, one less sync.
// Publish is DIRECT: activation lanes STG their half into g_hbuf (L2);
// one __syncthreads orders all stores before tid0's release.
// LAYER 0: input projection fused, x tile double-buffered (cp.async).
// LAYER 1: xg precomputed by k_gemm_xg; loads issued at step top.
constexpr int LSTM_SMEM0 = (128 * 264 + 128 * 520) * 2;  // 200704 B
constexpr int LSTM_SMEM1 = 128 * 520 * 2;                // 133120 B

template <int LAYER>
__global__ __launch_bounds__(256, 1) void k_lstm() {
    extern __shared__ __half smem[];
    __half* sWx = smem;                                        // layer0 only [128][264]
    __half* R   = (LAYER == 0) ? smem + 128 * 264 : smem;      // staging region
    __half* sW  = R;                                           // [128][520] init only
    __half* sA  = R;                                           // [16][520] (after init)
    __half* sX  = R + 16 * 520;                                // [2][16][264] layer0
    __half* sH  = R + 16 * 520 + 2 * 16 * 264;                 // [16][32]

    const __half* __restrict__ Whh = LAYER ? g_whh1p : g_whh0p;

    int tid = threadIdx.x;
    int lane = tid & 31, warp = tid >> 5;
    int grp = blockIdx.x >> 4;
    int c = blockIdx.x & 15;
    int r = lane >> 2, tg = lane & 3;
    int odd = tg & 1;
    int rowa = odd ? r + 8 : r;            // activation row this lane owns

    // stage W_hh slice rows [c*128, +128) into R
    {
        const uint4* src = (const uint4*)(Whh + (size_t)c * 128 * 512);
#pragma unroll
        for (int i = 0; i < 32; i++) {
            int u = tid + i * 256;
            int row = u >> 6, c4 = u & 63;
            ((uint4*)sW)[row * 65 + c4] = src[u];
        }
    }
    // layer0: load W_ih slice rows [c*128, +128) x 256 into sWx (stride 264)
    if (LAYER == 0) {
        const uint4* src = (const uint4*)(g_wih0p + (size_t)c * 128 * 256);
#pragma unroll
        for (int i = 0; i < 16; i++) {
            int u = tid + i * 256;
            int row = u >> 5, c4 = u & 31;
            *(uint4*)&sWx[row * 264 + c4 * 8] = src[u];
        }
    }
    __syncthreads();

    uint32_t R_u   = (uint32_t)__cvta_generic_to_shared(R);
    uint32_t sX_u  = (uint32_t)__cvta_generic_to_shared(sX);
    uint32_t sWx_u = (uint32_t)__cvta_generic_to_shared(sWx);
    uint32_t aAddr  = R_u  + (uint32_t)((((lane & 15) * 520) + ((lane >> 4) << 3)) << 1);
    uint32_t aAddrX = sX_u + (uint32_t)((((lane & 15) * 264) + ((lane >> 4) << 3)) << 1);
    const uint32_t xBufB = 16 * 264 * 2;   // bytes per sX buffer

    int bn = warp * 16 + ((lane >> 4) & 1) * 8 + (lane & 7);
    uint32_t bAddrX = sWx_u + (uint32_t)(((bn * 264) + ((lane >> 3) & 1) * 8) << 1);

    // preload ALL W_hh fragments into registers (warp owns 16 gate cols, K=512)
    uint32_t wf[32][4];
    {
        uint32_t sW_u = (uint32_t)__cvta_generic_to_shared(sW);
        uint32_t bAddr = sW_u + (uint32_t)(((bn * 520) + ((lane >> 3) & 1) * 8) << 1);
#pragma unroll
        for (int kt = 0; kt < 32; kt++)
            ldsm4(wf[kt][0], wf[kt][1], wf[kt][2], wf[kt][3], bAddr + (uint32_t)(kt * 32));
    }
    __syncthreads();   // frags read; R region may now be reused as sA/sX/sH

    // hidden units this lane owns (per nt) and their biases
    int uu[2];
    float4 b4[2];
#pragma unroll
    for (int nt = 0; nt < 2; nt++) {
        uu[nt] = warp * 4 + nt * 2 + (tg >> 1);
        if (LAYER == 0) b4[nt] = *(const float4*)&g_bias0[c * 128 + uu[nt] * 4];
        else            b4[nt] = make_float4(0.f, 0.f, 0.f, 0.f);
    }

    // x prefetch (layer0): 8 KB tile, 2 chunks/thread
    auto prefetch_x = [&](int t) {
        uint32_t dst = sX_u + (uint32_t)((t & 1)) * xBufB;
#pragma unroll
        for (int i = 0; i < 2; i++) {
            int u = tid + i * 256;
            int row = u >> 5, c4 = u & 31;
            cp16(dst + (uint32_t)((row * 264 + c4 * 8) * 2),
                 g_x16 + ((size_t)(grp * BSUB + row) * TT + t) * EE + c4 * 8);
        }
        cp_commit();
    };
    if (LAYER == 0) prefetch_x(0);

    float cs[2] = {0.f, 0.f};
    int* myflag = &g_flag[(grp * NSLICE + c) * 32];
    int p0 = 2 * warp, p1 = 2 * warp + 1;
    int* f0 = &g_flag[(grp * NSLICE + p0) * 32];
    int* f1 = &g_flag[(grp * NSLICE + p1) * 32];

    for (int t = 0; t < TT; t++) {
        float acc[2][4] = {};
        uint2 xgv[2];

        if (LAYER == 1) {
            // issue xg loads early (independent; overlap with poll + peer ldcv)
            int bgl = grp * BSUB + rowa;
#pragma unroll
            for (int nt = 0; nt < 2; nt++) {
                const __half* xp = g_xg + ((size_t)bgl * TT + t) * GG + c * 128 + uu[nt] * 4;
                xgv[nt] = __ldcs((const uint2*)xp);
            }
        }

        // 1) poll my 2 peers (flag >= t means they published h[t]); t=0 free
        if (t > 0) {
            int v0, v1;
            do {
                asm volatile("ld.acquire.gpu.global.s32 %0, [%1];" : "=r"(v0) : "l"(f0) : "memory");
                asm volatile("ld.acquire.gpu.global.s32 %0, [%1];" : "=r"(v1) : "l"(f1) : "memory");
            } while (v0 < t || v1 < t);
        }
        // 2) issue peer h loads into registers (latency overlapped by x-GEMM)
        uint4 hv0[2], hv1[2];
        {
            int par = t & 1;
            const uint4* s0 = (const uint4*)&g_hbuf[(((size_t)par * NGROUP + grp) * NSLICE + p0) * 512];
            const uint4* s1 = (const uint4*)&g_hbuf[(((size_t)par * NGROUP + grp) * NSLICE + p1) * 512];
#pragma unroll
            for (int j = 0; j < 2; j++) {
                hv0[j] = __ldcv(s0 + lane + j * 32);
                hv1[j] = __ldcv(s1 + lane + j * 32);
            }
        }

        if (LAYER == 0) {
            // 3) consume sX[t&1] (prefetched one step ago); x-GEMM overlaps ldcv
            asm volatile("cp.async.wait_group 0;");
            __syncthreads();
            uint32_t aX = aAddrX + (uint32_t)(t & 1) * xBufB;
#pragma unroll
            for (int kt = 0; kt < 16; kt++) {
                uint32_t ko = (uint32_t)(kt * 32);
                uint32_t a[4], w0, w1, w2, w3;
                ldsm4(a[0], a[1], a[2], a[3], aX + ko);
                ldsm4(w0, w1, w2, w3, bAddrX + ko);
                mma16816(acc[0], a, w0, w1);
                mma16816(acc[1], a, w2, w3);
            }
            if (t + 1 < TT) prefetch_x(t + 1);
        }

        // 4) store peer h into sA
#pragma unroll
        for (int j = 0; j < 2; j++) {
            int chunk = lane + j * 32;
            int row = chunk >> 2, c4 = chunk & 3;
            *(uint4*)&sA[row * 520 + p0 * 32 + c4 * 8] = hv0[j];
            *(uint4*)&sA[row * 520 + p1 * 32 + c4 * 8] = hv1[j];
        }
        __syncthreads();

        // 5) h-GEMM: gates += h_prev[16x512] @ Wslice^T (W frags in regs)
#pragma unroll
        for (int kt = 0; kt < 32; kt++) {
            uint32_t a[4];
            ldsm4(a[0], a[1], a[2], a[3], aAddr + (uint32_t)(kt * 32));
            mma16816(acc[0], a, wf[kt][0], wf[kt][1]);
            mma16816(acc[1], a, wf[kt][2], wf[kt][3]);
        }

        // 6) register-resident activations: pair-exchange via shfl.xor(1).
        //    even tg lane: owns (i,f) of row r; receives (g,o) of row r from partner.
        //    odd  tg lane: owns (g,o) of row r+8; receives (i,f) of row r+8.
        {
            int par = (t + 1) & 1;
            __half* hb = &g_hbuf[(((size_t)par * NGROUP + grp) * NSLICE + c) * 512];
#pragma unroll
            for (int nt = 0; nt < 2; nt++) {
                float s0 = __shfl_xor_sync(0xffffffffu, odd ? acc[nt][0] : acc[nt][2], 1);
                float s1 = __shfl_xor_sync(0xffffffffu, odd ? acc[nt][1] : acc[nt][3], 1);
                float ip, fp, gp, op;
                if (odd) { ip = s0;         fp = s1;         gp = acc[nt][2]; op = acc[nt][3]; }
                else     { ip = acc[nt][0]; fp = acc[nt][1]; gp = s0;         op = s1;         }
                if (LAYER == 0) {
                    ip += b4[nt].x; fp += b4[nt].y; gp += b4[nt].z; op += b4[nt].w;
                } else {
                    __half2 x01 = *(__half2*)&xgv[nt].x;
                    __half2 x23 = *(__half2*)&xgv[nt].y;
                    ip += __low2float(x01);  fp += __high2float(x01);
                    gp += __low2float(x23);  op += __high2float(x23);
                }
                float ig = sigm(ip), fg = sigm(fp), gvv = tanhfast(gp), og = sigm(op);
                float cv = fg * cs[nt] + ig * gvv;
                cs[nt] = cv;
                float hv = og * tanhfast(cv);
                __half hh = __float2half(hv);
                sH[rowa * 32 + uu[nt]] = hh;       // staging for g_h1/g_hlast
                hb[rowa * 32 + uu[nt]] = hh;       // direct publish (L2)
            }
        }
        // 7) order all publish stores, release; off-path writers stream g_h1
        __syncthreads();
        if (tid == 0)
            asm volatile("st.release.gpu.global.s32 [%0], %1;"
                         :: "l"(myflag), "r"(t + 1) : "memory");
        if (LAYER == 0 && tid < 64) {
            int row = tid >> 2, c4 = tid & 3;
            uint4 hv4 = *(uint4*)&sH[row * 32 + c4 * 8];
            int bgl = grp * BSUB + row;
            __stcs((uint4*)&g_h1[((size_t)bgl * TT + t) * HH + c * 32 + c4 * 8], hv4);
        }
        if (LAYER == 1 && t == TT - 1 && tid < 64) {
            int row = tid >> 2, c4 = tid & 3;
            int bgl = grp * BSUB + row;
            const __half* hp = &sH[row * 32 + c4 * 8];
            float* dp = &g_hlast[bgl * HH + c * 32 + c4 * 8];
#pragma unroll
            for (int e = 0; e < 8; e++) dp[e] = __half2float(hp[e]);
        }
        __syncthreads();
    }
}

// ---------------- final FC + sigmoid ----------------
__global__ void k_fc(const float* __restrict__ wfc, const float* __restrict__ bfc,
                     float* __restrict__ out) {
    int w = blockIdx.x * 4 + (threadIdx.x >> 5);
    int lane = threadIdx.x & 31;
    if (w < BB) {
        float s = 0.f;
        for (int k = lane; k < HH; k += 32) s += g_hlast[w * HH + k] * wfc[k];
#pragma unroll
        for (int o = 16; o; o >>= 1) s += __shfl_xor_sync(0xffffffffu, s, o);
        if (lane == 0) out[w] = 1.f / (1.f + __expf(-(s + bfc[0])));
    }
}

// ---------------- launch ----------------
extern "C" void kernel_launch(void* const* d_in, const int* in_sizes, int n_in,
                              void* d_out, int out_size) {
    const float* x    = (const float*)d_in[0];
    const float* wih0 = (const float*)d_in[1];
    const float* whh0 = (const float*)d_in[2];
    const float* bih0 = (const float*)d_in[3];
    const float* bhh0 = (const float*)d_in[4];
    const float* wih1 = (const float*)d_in[5];
    const float* whh1 = (const float*)d_in[6];
    const float* bih1 = (const float*)d_in[7];
    const float* bhh1 = (const float*)d_in[8];
    const float* wfc  = (const float*)d_in[9];
    const float* bfc  = (const float*)d_in[10];
    float* out = (float*)d_out;

    cudaFuncSetAttribute(k_lstm<0>, cudaFuncAttributeMaxDynamicSharedMemorySize, LSTM_SMEM0);
    cudaFuncSetAttribute(k_lstm<1>, cudaFuncAttributeMaxDynamicSharedMemorySize, LSTM_SMEM1);
    cudaFuncSetAttribute(k_gemm_xg<HH>, cudaFuncAttributeMaxDynamicSharedMemorySize, GEMM_SMEM);

    // prep: fp16 conversions + gate-column permutation
    k_conv_x<<<(MR * EE + 255) / 256, 256>>>(x);
    k_prep_w<<<dim3((GG * HH + 255) / 256, 4), 256>>>(wih0, whh0, wih1, whh1);
    k_prep_b<<<dim3((GG + 255) / 256, 2), 256>>>(bih0, bhh0, bih1, bhh1);

    // layer 1 (input projection fused, x double-buffered)
    k_reset<<<256, 256>>>();
    k_lstm<0><<<NGROUP * NSLICE, 256, LSTM_SMEM0>>>();

    // layer 2
    k_gemm_xg<HH><<<dim3(GG / 128, MR / 128), 256, GEMM_SMEM>>>();
    k_reset<<<256, 256>>>();
    k_lstm<1><<<NGROUP * NSLICE, 256, LSTM_SMEM1>>>();

    // head
    k_fc<<<(BB + 3) / 4, 128>>>(wfc, bfc, out);
}

// round 13
// speedup vs baseline: 1.0270x; 1.0270x over previous
#include <cuda_runtime.h>
#include <cuda_fp16.h>
#include <stdint.h>

// Problem constants
constexpr int BB = 128;    // batch
constexpr int TT = 512;    // seq len
constexpr int EE = 256;    // embed
constexpr int HH = 512;    // hidden
constexpr int GG = 2048;   // 4*H gates
constexpr int MR = BB * TT;  // 65536 rows

constexpr int NGROUP = 8;   // batch groups
constexpr int NSLICE = 16;  // CTAs per group
constexpr int BSUB   = 16;  // batch rows per group

// ---------------- static device scratch (allocation-free) ----------------
__device__ __half g_x16[(size_t)MR * EE];
__device__ __half g_h1 [(size_t)MR * HH];
__device__ __half g_xg [(size_t)MR * GG];     // fp16 xg, layer-2 only
__device__ __half g_wih0p[GG * EE];
__device__ __half g_wih1p[GG * HH];
__device__ __half g_whh0p[GG * HH];
__device__ __half g_whh1p[GG * HH];
__device__ float  g_bias0[GG];
__device__ float  g_bias1[GG];
// h exchange, per-peer contiguous: [parity][group][peer][row16][32 halves]
__device__ __half g_hbuf[2 * NGROUP * NSLICE * BSUB * 32];
__device__ float  g_hlast[BB * HH];
__device__ int    g_flag[NGROUP * NSLICE * 32]; // 128B-spread barrier flags

// Column permutation: new index m -> original gate column n
// m = c*128 + u*4 + q  (c = CTA slice 0..15, u = hidden-in-slice 0..31, q = gate 0..3)
// n = q*512 + c*32 + u
__device__ __forceinline__ int perm_orig(int m) {
    int cc = m >> 7, l = m & 127, u = l >> 2, q = l & 3;
    return q * 512 + cc * 32 + u;
}

// ---------------- prep kernels ----------------
__global__ void k_conv_x(const float* __restrict__ x) {
    size_t i = (size_t)blockIdx.x * blockDim.x + threadIdx.x;
    if (i < (size_t)MR * EE) g_x16[i] = __float2half(x[i]);
}

__global__ void k_prep_w(const float* __restrict__ wih0, const float* __restrict__ whh0,
                         const float* __restrict__ wih1, const float* __restrict__ whh1) {
    int which = blockIdx.y;
    size_t i = (size_t)blockIdx.x * blockDim.x + threadIdx.x;
    const float* src; __half* dst; int K;
    if      (which == 0) { src = wih0; dst = g_wih0p; K = EE; }
    else if (which == 1) { src = whh0; dst = g_whh0p; K = HH; }
    else if (which == 2) { src = wih1; dst = g_wih1p; K = HH; }
    else                 { src = whh1; dst = g_whh1p; K = HH; }
    if (i >= (size_t)GG * K) return;
    int m = (int)(i / K), k = (int)(i % K);
    int n = perm_orig(m);
    dst[i] = __float2half(src[(size_t)n * K + k]);
}

__global__ void k_prep_b(const float* __restrict__ bih0, const float* __restrict__ bhh0,
                         const float* __restrict__ bih1, const float* __restrict__ bhh1) {
    int m = blockIdx.x * blockDim.x + threadIdx.x;
    if (m >= GG) return;
    int n = perm_orig(m);
    if (blockIdx.y == 0) g_bias0[m] = bih0[n] + bhh0[n];
    else                 g_bias1[m] = bih1[n] + bhh1[n];
}

__global__ void k_reset() {
    int i = blockIdx.x * blockDim.x + threadIdx.x;
    if (i < 2 * BB * HH / 2) ((uint32_t*)g_hbuf)[i] = 0u;
    if (i < NGROUP * NSLICE * 32) g_flag[i] = 0;
}

// ---------------- asm helpers ----------------
__device__ __forceinline__ void mma16816(float* d, const uint32_t* a, uint32_t b0, uint32_t b1) {
    asm volatile(
        "mma.sync.aligned.m16n8k16.row.col.f32.f16.f16.f32 "
        "{%0,%1,%2,%3},{%4,%5,%6,%7},{%8,%9},{%0,%1,%2,%3};"
        : "+f"(d[0]), "+f"(d[1]), "+f"(d[2]), "+f"(d[3])
        : "r"(a[0]), "r"(a[1]), "r"(a[2]), "r"(a[3]), "r"(b0), "r"(b1));
}

__device__ __forceinline__ void ldsm4(uint32_t& r0, uint32_t& r1, uint32_t& r2, uint32_t& r3,
                                      uint32_t addr) {
    asm volatile("ldmatrix.sync.aligned.m8n8.x4.shared.b16 {%0,%1,%2,%3}, [%4];"
                 : "=r"(r0), "=r"(r1), "=r"(r2), "=r"(r3) : "r"(addr));
}

__device__ __forceinline__ void cp16(uint32_t dst, const void* src) {
    asm volatile("cp.async.cg.shared.global [%0], [%1], 16;" :: "r"(dst), "l"(src));
}
__device__ __forceinline__ void cp_commit() { asm volatile("cp.async.commit_group;"); }

__device__ __forceinline__ float tanhfast(float x) {
    float y;
    asm("tanh.approx.f32 %0, %1;" : "=f"(y) : "f"(x));
    return y;
}
__device__ __forceinline__ float sigm(float x) {
    return fmaf(0.5f, tanhfast(0.5f * x), 0.5f);
}

// ---------------- xg GEMM (layer 2 only): C[M,2048] = h1[M,512] @ W^T + bias ------------
// BM=128, BN=128, BK=32, 256 threads (8 warps: 4 M x 2 N, warp tile 32x64)
// 4-stage cp.async ring, loop-split tail waits; smem-staged coalesced epilogue.
constexpr int GEMM_STAGE = (128 + 128) * 40;           // halves per stage
constexpr int GEMM_SMEM  = 4 * GEMM_STAGE * 2;         // 81920 B

template <int K>
__global__ __launch_bounds__(256, 2) void k_gemm_xg() {
    const __half* __restrict__ A = g_h1;
    const __half* __restrict__ W = g_wih1p;
    const float*  __restrict__ bias = g_bias1;

    extern __shared__ __align__(16) __half gsm[];

    int tid = threadIdx.x;
    int m0 = blockIdx.y * 128;
    int n0 = blockIdx.x * 128;
    int lane = tid & 31, warp = tid >> 5;
    int wm = warp & 3, wn = warp >> 2;
    int r = lane >> 2, tg = lane & 3;

    uint32_t gsmu = (uint32_t)__cvta_generic_to_shared(gsm);
    const uint32_t stageB = GEMM_STAGE * 2;

    uint32_t laneA = (uint32_t)(((lane & 15) * 40 + ((lane >> 4) << 3)) << 1);
    int bnn = wn * 64 + ((lane >> 4) & 1) * 8 + (lane & 7);
    uint32_t laneB = (uint32_t)((bnn * 40 + ((lane >> 3) & 1) * 8) << 1);

    float acc[2][8][4] = {};
    constexpr int KT = K / 32;

    auto load_stage = [&](int st, int kt) {
        uint32_t base = gsmu + st * stageB;
#pragma unroll
        for (int i = 0; i < 2; i++) {
            int chunk = tid + i * 256;
            int row = chunk >> 2, c4 = chunk & 3;
            cp16(base + (uint32_t)((row * 40 + c4 * 8) * 2),
                 A + (size_t)(m0 + row) * K + kt * 32 + c4 * 8);
        }
#pragma unroll
        for (int i = 0; i < 2; i++) {
            int chunk = tid + i * 256;
            int row = chunk >> 2, c4 = chunk & 3;
            cp16(base + (uint32_t)(128 * 80) + (uint32_t)((row * 40 + c4 * 8) * 2),
                 W + (size_t)(n0 + row) * K + kt * 32 + c4 * 8);
        }
        cp_commit();
    };

    auto consume = [&](int st) {
        uint32_t abase = gsmu + st * stageB;
        uint32_t bbase = abase + (uint32_t)(128 * 80);
#pragma unroll
        for (int kk = 0; kk < 2; kk++) {
            uint32_t kko = (uint32_t)(kk * 32);
            uint32_t a[2][4];
#pragma unroll
            for (int mt = 0; mt < 2; mt++) {
                uint32_t addr = abase + (uint32_t)(((wm * 32 + mt * 16) * 40) << 1) + laneA + kko;
                ldsm4(a[mt][0], a[mt][1], a[mt][2], a[mt][3], addr);
            }
            uint32_t p[4][4];
#pragma unroll
            for (int q = 0; q < 4; q++)
                ldsm4(p[q][0], p[q][1], p[q][2], p[q][3],
                      bbase + laneB + (uint32_t)(q * 16 * 80) + kko);
#pragma unroll
            for (int mt = 0; mt < 2; mt++)
#pragma unroll
                for (int q = 0; q < 4; q++) {
                    mma16816(acc[mt][2 * q],     a[mt], p[q][0], p[q][1]);
                    mma16816(acc[mt][2 * q + 1], a[mt], p[q][2], p[q][3]);
                }
        }
    };

    load_stage(0, 0);
    load_stage(1, 1);
    load_stage(2, 2);

    int st = 0;
#pragma unroll 1
    for (int kt = 0; kt < KT - 3; kt++) {
        asm volatile("cp.async.wait_group 2;");
        __syncthreads();
        load_stage((st + 3) & 3, kt + 3);
        consume(st);
        st = (st + 1) & 3;
    }
    asm volatile("cp.async.wait_group 2;");
    __syncthreads();
    consume(st); st = (st + 1) & 3;
    asm volatile("cp.async.wait_group 1;");
    __syncthreads();
    consume(st); st = (st + 1) & 3;
    asm volatile("cp.async.wait_group 0;");
    __syncthreads();
    consume(st);

    // epilogue: bias add, stage in smem (stride 136 halves, conflict-free),
    // then fully-coalesced uint4 streaming stores.
    __syncthreads();   // stage buffers now free
    __half* sC = gsm;  // [128][136]
#pragma unroll
    for (int mt = 0; mt < 2; mt++)
#pragma unroll
        for (int j = 0; j < 8; j++) {
            int m = wm * 32 + mt * 16 + r;
            int n = wn * 64 + (j >> 1) * 16 + (j & 1) * 8 + tg * 2;
            float b0 = bias[n0 + n], b1 = bias[n0 + n + 1];
            *(__half2*)&sC[m * 136 + n] =
                __floats2half2_rn(acc[mt][j][0] + b0, acc[mt][j][1] + b1);
            *(__half2*)&sC[(m + 8) * 136 + n] =
                __floats2half2_rn(acc[mt][j][2] + b0, acc[mt][j][3] + b1);
        }
    __syncthreads();
#pragma unroll
    for (int i = 0; i < 8; i++) {
        int ch = tid + i * 256;            // 2048 chunks of 16B
        int row = ch >> 4, off = ch & 15;
        uint4 v = *(uint4*)&sC[row * 136 + off * 8];
        *(uint4*)&g_xg[(size_t)(m0 + row) * GG + n0 + off * 8] = v;
    }
}

// ---------------- persistent LSTM recurrence ----------------
// 128 CTAs = 8 groups x 16 slices, 256 threads (8 warps, 16 gate cols/warp).
// CTA (g,c): batch rows [g*16,g*16+16), hidden [c*32,c*32+32), permuted gate
// cols [c*128,c*128+128). W_hh fragments in REGISTERS (128/thread).
// Register-resident activations via shfl.xor(1) pair exchange (no gate smem).
// Publish: activations write sH; one sync; 64 writers stream uint4 -> g_hbuf,
// bar.sync(1,64), tid0 releases. NO tail sync — warps 2..7 start the next
// step's poll while writers drain (top-of-step sync is the rendezvous).
// LAYER 0: input projection fused, x tile double-buffered (cp.async).
// LAYER 1: xg precomputed by k_gemm_xg; loads issued at step top.
constexpr int LSTM_SMEM0 = (128 * 264 + 128 * 520) * 2;  // 200704 B
constexpr int LSTM_SMEM1 = 128 * 520 * 2;                // 133120 B

template <int LAYER>
__global__ __launch_bounds__(256, 1) void k_lstm() {
    extern __shared__ __half smem[];
    __half* sWx = smem;                                        // layer0 only [128][264]
    __half* R   = (LAYER == 0) ? smem + 128 * 264 : smem;      // staging region
    __half* sW  = R;                                           // [128][520] init only
    __half* sA  = R;                                           // [16][520] (after init)
    __half* sX  = R + 16 * 520;                                // [2][16][264] layer0
    __half* sH  = R + 16 * 520 + 2 * 16 * 264;                 // [16][32]

    const __half* __restrict__ Whh = LAYER ? g_whh1p : g_whh0p;

    int tid = threadIdx.x;
    int lane = tid & 31, warp = tid >> 5;
    int grp = blockIdx.x >> 4;
    int c = blockIdx.x & 15;
    int r = lane >> 2, tg = lane & 3;
    int odd = tg & 1;
    int rowa = odd ? r + 8 : r;            // activation row this lane owns

    // stage W_hh slice rows [c*128, +128) into R
    {
        const uint4* src = (const uint4*)(Whh + (size_t)c * 128 * 512);
#pragma unroll
        for (int i = 0; i < 32; i++) {
            int u = tid + i * 256;
            int row = u >> 6, c4 = u & 63;
            ((uint4*)sW)[row * 65 + c4] = src[u];
        }
    }
    // layer0: load W_ih slice rows [c*128, +128) x 256 into sWx (stride 264)
    if (LAYER == 0) {
        const uint4* src = (const uint4*)(g_wih0p + (size_t)c * 128 * 256);
#pragma unroll
        for (int i = 0; i < 16; i++) {
            int u = tid + i * 256;
            int row = u >> 5, c4 = u & 31;
            *(uint4*)&sWx[row * 264 + c4 * 8] = src[u];
        }
    }
    __syncthreads();

    uint32_t R_u   = (uint32_t)__cvta_generic_to_shared(R);
    uint32_t sX_u  = (uint32_t)__cvta_generic_to_shared(sX);
    uint32_t sWx_u = (uint32_t)__cvta_generic_to_shared(sWx);
    uint32_t aAddr  = R_u  + (uint32_t)((((lane & 15) * 520) + ((lane >> 4) << 3)) << 1);
    uint32_t aAddrX = sX_u + (uint32_t)((((lane & 15) * 264) + ((lane >> 4) << 3)) << 1);
    const uint32_t xBufB = 16 * 264 * 2;   // bytes per sX buffer

    int bn = warp * 16 + ((lane >> 4) & 1) * 8 + (lane & 7);
    uint32_t bAddrX = sWx_u + (uint32_t)(((bn * 264) + ((lane >> 3) & 1) * 8) << 1);

    // preload ALL W_hh fragments into registers (warp owns 16 gate cols, K=512)
    uint32_t wf[32][4];
    {
        uint32_t sW_u = (uint32_t)__cvta_generic_to_shared(sW);
        uint32_t bAddr = sW_u + (uint32_t)(((bn * 520) + ((lane >> 3) & 1) * 8) << 1);
#pragma unroll
        for (int kt = 0; kt < 32; kt++)
            ldsm4(wf[kt][0], wf[kt][1], wf[kt][2], wf[kt][3], bAddr + (uint32_t)(kt * 32));
    }
    __syncthreads();   // frags read; R region may now be reused as sA/sX/sH

    // hidden units this lane owns (per nt) and their biases
    int uu[2];
    float4 b4[2];
#pragma unroll
    for (int nt = 0; nt < 2; nt++) {
        uu[nt] = warp * 4 + nt * 2 + (tg >> 1);
        if (LAYER == 0) b4[nt] = *(const float4*)&g_bias0[c * 128 + uu[nt] * 4];
        else            b4[nt] = make_float4(0.f, 0.f, 0.f, 0.f);
    }

    // x prefetch (layer0): 8 KB tile, 2 chunks/thread
    auto prefetch_x = [&](int t) {
        uint32_t dst = sX_u + (uint32_t)((t & 1)) * xBufB;
#pragma unroll
        for (int i = 0; i < 2; i++) {
            int u = tid + i * 256;
            int row = u >> 5, c4 = u & 31;
            cp16(dst + (uint32_t)((row * 264 + c4 * 8) * 2),
                 g_x16 + ((size_t)(grp * BSUB + row) * TT + t) * EE + c4 * 8);
        }
        cp_commit();
    };
    if (LAYER == 0) prefetch_x(0);

    float cs[2] = {0.f, 0.f};
    int* myflag = &g_flag[(grp * NSLICE + c) * 32];
    int p0 = 2 * warp, p1 = 2 * warp + 1;
    int* f0 = &g_flag[(grp * NSLICE + p0) * 32];
    int* f1 = &g_flag[(grp * NSLICE + p1) * 32];

    for (int t = 0; t < TT; t++) {
        float acc[2][4] = {};
        uint2 xgv[2];

        if (LAYER == 1) {
            // issue xg loads early (independent; overlap with poll + peer ldcv)
            int bgl = grp * BSUB + rowa;
#pragma unroll
            for (int nt = 0; nt < 2; nt++) {
                const __half* xp = g_xg + ((size_t)bgl * TT + t) * GG + c * 128 + uu[nt] * 4;
                xgv[nt] = __ldcs((const uint2*)xp);
            }
        }

        // 1) poll my 2 peers (flag >= t means they published h[t]); t=0 free
        if (t > 0) {
            int v0, v1;
            do {
                asm volatile("ld.acquire.gpu.global.s32 %0, [%1];" : "=r"(v0) : "l"(f0) : "memory");
                asm volatile("ld.acquire.gpu.global.s32 %0, [%1];" : "=r"(v1) : "l"(f1) : "memory");
            } while (v0 < t || v1 < t);
        }
        // 2) issue peer h loads into registers (latency overlapped by x-GEMM)
        uint4 hv0[2], hv1[2];
        {
            int par = t & 1;
            const uint4* s0 = (const uint4*)&g_hbuf[(((size_t)par * NGROUP + grp) * NSLICE + p0) * 512];
            const uint4* s1 = (const uint4*)&g_hbuf[(((size_t)par * NGROUP + grp) * NSLICE + p1) * 512];
#pragma unroll
            for (int j = 0; j < 2; j++) {
                hv0[j] = __ldcv(s0 + lane + j * 32);
                hv1[j] = __ldcv(s1 + lane + j * 32);
            }
        }

        if (LAYER == 0) {
            // 3) consume sX[t&1] (prefetched one step ago); x-GEMM overlaps ldcv
            asm volatile("cp.async.wait_group 0;");
            __syncthreads();
            uint32_t aX = aAddrX + (uint32_t)(t & 1) * xBufB;
#pragma unroll
            for (int kt = 0; kt < 16; kt++) {
                uint32_t ko = (uint32_t)(kt * 32);
                uint32_t a[4], w0, w1, w2, w3;
                ldsm4(a[0], a[1], a[2], a[3], aX + ko);
                ldsm4(w0, w1, w2, w3, bAddrX + ko);
                mma16816(acc[0], a, w0, w1);
                mma16816(acc[1], a, w2, w3);
            }
            if (t + 1 < TT) prefetch_x(t + 1);
        }

        // 4) store peer h into sA
#pragma unroll
        for (int j = 0; j < 2; j++) {
            int chunk = lane + j * 32;
            int row = chunk >> 2, c4 = chunk & 3;
            *(uint4*)&sA[row * 520 + p0 * 32 + c4 * 8] = hv0[j];
            *(uint4*)&sA[row * 520 + p1 * 32 + c4 * 8] = hv1[j];
        }
        __syncthreads();   // rendezvous: also orders prior step's publish reads

        // 5) h-GEMM: gates += h_prev[16x512] @ Wslice^T (W frags in regs)
#pragma unroll
        for (int kt = 0; kt < 32; kt++) {
            uint32_t a[4];
            ldsm4(a[0], a[1], a[2], a[3], aAddr + (uint32_t)(kt * 32));
            mma16816(acc[0], a, wf[kt][0], wf[kt][1]);
            mma16816(acc[1], a, wf[kt][2], wf[kt][3]);
        }

        // 6) register-resident activations: pair-exchange via shfl.xor(1).
        //    even tg lane: owns (i,f) of row r; receives (g,o) of row r.
        //    odd  tg lane: owns (g,o) of row r+8; receives (i,f) of row r+8.
#pragma unroll
        for (int nt = 0; nt < 2; nt++) {
            float s0 = __shfl_xor_sync(0xffffffffu, odd ? acc[nt][0] : acc[nt][2], 1);
            float s1 = __shfl_xor_sync(0xffffffffu, odd ? acc[nt][1] : acc[nt][3], 1);
            float ip, fp, gp, op;
            if (odd) { ip = s0;         fp = s1;         gp = acc[nt][2]; op = acc[nt][3]; }
            else     { ip = acc[nt][0]; fp = acc[nt][1]; gp = s0;         op = s1;         }
            if (LAYER == 0) {
                ip += b4[nt].x; fp += b4[nt].y; gp += b4[nt].z; op += b4[nt].w;
            } else {
                __half2 x01 = *(__half2*)&xgv[nt].x;
                __half2 x23 = *(__half2*)&xgv[nt].y;
                ip += __low2float(x01);  fp += __high2float(x01);
                gp += __low2float(x23);  op += __high2float(x23);
            }
            float ig = sigm(ip), fg = sigm(fp), gvv = tanhfast(gp), og = sigm(op);
            float cv = fg * cs[nt] + ig * gvv;
            cs[nt] = cv;
            float hv = og * tanhfast(cv);
            sH[rowa * 32 + uu[nt]] = __float2half(hv);
        }
        __syncthreads();   // all sH writes visible to the 64 writers

        // 7) coalesced publish (64 writers) + release. NO tail sync: warps 2..7
        //    proceed to next step's poll; top-of-step sync is the rendezvous.
        if (tid < 64) {
            int row = tid >> 2, c4 = tid & 3;
            uint4 hv4 = *(uint4*)&sH[row * 32 + c4 * 8];
            int par = (t + 1) & 1;
            *(uint4*)&g_hbuf[(((size_t)par * NGROUP + grp) * NSLICE + c) * 512
                             + row * 32 + c4 * 8] = hv4;
            asm volatile("bar.sync 1, 64;");
            if (tid == 0)
                asm volatile("st.release.gpu.global.s32 [%0], %1;"
                             :: "l"(myflag), "r"(t + 1) : "memory");
            int bgl = grp * BSUB + row;
            if (LAYER == 0)
                __stcs((uint4*)&g_h1[((size_t)bgl * TT + t) * HH + c * 32 + c4 * 8], hv4);
            if (LAYER == 1 && t == TT - 1) {
                const __half* hp = &sH[row * 32 + c4 * 8];
                float* dp = &g_hlast[bgl * HH + c * 32 + c4 * 8];
#pragma unroll
                for (int e = 0; e < 8; e++) dp[e] = __half2float(hp[e]);
            }
        }
    }
}

// ---------------- final FC + sigmoid ----------------
__global__ void k_fc(const float* __restrict__ wfc, const float* __restrict__ bfc,
                     float* __restrict__ out) {
    int w = blockIdx.x * 4 + (threadIdx.x >> 5);
    int lane = threadIdx.x & 31;
    if (w < BB) {
        float s = 0.f;
        for (int k = lane; k < HH; k += 32) s += g_hlast[w * HH + k] * wfc[k];
#pragma unroll
        for (int o = 16; o; o >>= 1) s += __shfl_xor_sync(0xffffffffu, s, o);
        if (lane == 0) out[w] = 1.f / (1.f + __expf(-(s + bfc[0])));
    }
}

// ---------------- launch ----------------
extern "C" void kernel_launch(void* const* d_in, const int* in_sizes, int n_in,
                              void* d_out, int out_size) {
    const float* x    = (const float*)d_in[0];
    const float* wih0 = (const float*)d_in[1];
    const float* whh0 = (const float*)d_in[2];
    const float* bih0 = (const float*)d_in[3];
    const float* bhh0 = (const float*)d_in[4];
    const float* wih1 = (const float*)d_in[5];
    const float* whh1 = (const float*)d_in[6];
    const float* bih1 = (const float*)d_in[7];
    const float* bhh1 = (const float*)d_in[8];
    const float* wfc  = (const float*)d_in[9];
    const float* bfc  = (const float*)d_in[10];
    float* out = (float*)d_out;

    cudaFuncSetAttribute(k_lstm<0>, cudaFuncAttributeMaxDynamicSharedMemorySize, LSTM_SMEM0);
    cudaFuncSetAttribute(k_lstm<1>, cudaFuncAttributeMaxDynamicSharedMemorySize, LSTM_SMEM1);
    cudaFuncSetAttribute(k_gemm_xg<HH>, cudaFuncAttributeMaxDynamicSharedMemorySize, GEMM_SMEM);

    // prep: fp16 conversions + gate-column permutation
    k_conv_x<<<(MR * EE + 255) / 256, 256>>>(x);
    k_prep_w<<<dim3((GG * HH + 255) / 256, 4), 256>>>(wih0, whh0, wih1, whh1);
    k_prep_b<<<dim3((GG + 255) / 256, 2), 256>>>(bih0, bhh0, bih1, bhh1);

    // layer 1 (input projection fused, x double-buffered)
    k_reset<<<256, 256>>>();
    k_lstm<0><<<NGROUP * NSLICE, 256, LSTM_SMEM0>>>();

    // layer 2
    k_gemm_xg<HH><<<dim3(GG / 128, MR / 128), 256, GEMM_SMEM>>>();
    k_reset<<<256, 256>>>();
    k_lstm<1><<<NGROUP * NSLICE, 256, LSTM_SMEM1>>>();

    // head
    k_fc<<<(BB + 3) / 4, 128>>>(wfc, bfc, out);
}

// round 14
// speedup vs baseline: 1.0317x; 1.0046x over previous
#include <cuda_runtime.h>
#include <cuda_fp16.h>
#include <stdint.h>

// Problem constants
constexpr int BB = 128;    // batch
constexpr int TT = 512;    // seq len
constexpr int EE = 256;    // embed
constexpr int HH = 512;    // hidden
constexpr int GG = 2048;   // 4*H gates
constexpr int MR = BB * TT;  // 65536 rows

constexpr int NGROUP = 8;   // batch groups
constexpr int NSLICE = 16;  // CTAs per group
constexpr int BSUB   = 16;  // batch rows per group

// ---------------- static device scratch (allocation-free) ----------------
__device__ __half g_x16[(size_t)MR * EE];
__device__ __half g_h1 [(size_t)MR * HH];
__device__ __half g_xg [(size_t)MR * GG];     // fp16 xg, layer-2 only
__device__ __half g_wih0p[GG * EE];
__device__ __half g_wih1p[GG * HH];
__device__ __half g_whh0p[GG * HH];
__device__ __half g_whh1p[GG * HH];
__device__ float  g_bias0[GG];
__device__ float  g_bias1[GG];
// h exchange, per-peer contiguous: [parity][group][peer][row16][32 halves]
__device__ __half g_hbuf[2 * NGROUP * NSLICE * BSUB * 32];
__device__ float  g_hlast[BB * HH];
__device__ int    g_flag[NGROUP * NSLICE * 32]; // 128B-spread barrier flags

// Column permutation: new index m -> original gate column n
// m = c*128 + u*4 + q  (c = CTA slice 0..15, u = hidden-in-slice 0..31, q = gate 0..3)
// n = q*512 + c*32 + u
__device__ __forceinline__ int perm_orig(int m) {
    int cc = m >> 7, l = m & 127, u = l >> 2, q = l & 3;
    return q * 512 + cc * 32 + u;
}

// ---------------- prep kernels ----------------
__global__ void k_conv_x(const float* __restrict__ x) {
    size_t i = (size_t)blockIdx.x * blockDim.x + threadIdx.x;
    if (i < (size_t)MR * EE) g_x16[i] = __float2half(x[i]);
}

__global__ void k_prep_w(const float* __restrict__ wih0, const float* __restrict__ whh0,
                         const float* __restrict__ wih1, const float* __restrict__ whh1) {
    int which = blockIdx.y;
    size_t i = (size_t)blockIdx.x * blockDim.x + threadIdx.x;
    const float* src; __half* dst; int K;
    if      (which == 0) { src = wih0; dst = g_wih0p; K = EE; }
    else if (which == 1) { src = whh0; dst = g_whh0p; K = HH; }
    else if (which == 2) { src = wih1; dst = g_wih1p; K = HH; }
    else                 { src = whh1; dst = g_whh1p; K = HH; }
    if (i >= (size_t)GG * K) return;
    int m = (int)(i / K), k = (int)(i % K);
    int n = perm_orig(m);
    dst[i] = __float2half(src[(size_t)n * K + k]);
}

__global__ void k_prep_b(const float* __restrict__ bih0, const float* __restrict__ bhh0,
                         const float* __restrict__ bih1, const float* __restrict__ bhh1) {
    int m = blockIdx.x * blockDim.x + threadIdx.x;
    if (m >= GG) return;
    int n = perm_orig(m);
    if (blockIdx.y == 0) g_bias0[m] = bih0[n] + bhh0[n];
    else                 g_bias1[m] = bih1[n] + bhh1[n];
}

__global__ void k_reset() {
    int i = blockIdx.x * blockDim.x + threadIdx.x;
    if (i < 2 * BB * HH / 2) ((uint32_t*)g_hbuf)[i] = 0u;
    if (i < NGROUP * NSLICE * 32) g_flag[i] = 0;
}

// ---------------- asm helpers ----------------
__device__ __forceinline__ void mma16816(float* d, const uint32_t* a, uint32_t b0, uint32_t b1) {
    asm volatile(
        "mma.sync.aligned.m16n8k16.row.col.f32.f16.f16.f32 "
        "{%0,%1,%2,%3},{%4,%5,%6,%7},{%8,%9},{%0,%1,%2,%3};"
        : "+f"(d[0]), "+f"(d[1]), "+f"(d[2]), "+f"(d[3])
        : "r"(a[0]), "r"(a[1]), "r"(a[2]), "r"(a[3]), "r"(b0), "r"(b1));
}

__device__ __forceinline__ void ldsm4(uint32_t& r0, uint32_t& r1, uint32_t& r2, uint32_t& r3,
                                      uint32_t addr) {
    asm volatile("ldmatrix.sync.aligned.m8n8.x4.shared.b16 {%0,%1,%2,%3}, [%4];"
                 : "=r"(r0), "=r"(r1), "=r"(r2), "=r"(r3) : "r"(addr));
}

__device__ __forceinline__ void cp16(uint32_t dst, const void* src) {
    asm volatile("cp.async.cg.shared.global [%0], [%1], 16;" :: "r"(dst), "l"(src));
}
__device__ __forceinline__ void cp_commit() { asm volatile("cp.async.commit_group;"); }

__device__ __forceinline__ float tanhfast(float x) {
    float y;
    asm("tanh.approx.f32 %0, %1;" : "=f"(y) : "f"(x));
    return y;
}
__device__ __forceinline__ float sigm(float x) {
    return fmaf(0.5f, tanhfast(0.5f * x), 0.5f);
}

// ---------------- xg GEMM (layer 2 only): C[M,2048] = h1[M,512] @ W^T + bias ------------
// BM=128, BN=128, BK=32, 128 threads (4 warps: 2 M x 2 N, warp tile 64x64).
// Denser HMMA:LDSM ratio (32:8 per kk vs 16:6 before). 4-stage cp.async ring,
// loop-split tail waits; smem-staged coalesced epilogue. 2 CTAs/SM.
constexpr int GEMM_STAGE = (128 + 128) * 40;           // halves per stage
constexpr int GEMM_SMEM  = 4 * GEMM_STAGE * 2;         // 81920 B

template <int K>
__global__ __launch_bounds__(128, 2) void k_gemm_xg() {
    const __half* __restrict__ A = g_h1;
    const __half* __restrict__ W = g_wih1p;
    const float*  __restrict__ bias = g_bias1;

    extern __shared__ __align__(16) __half gsm[];

    int tid = threadIdx.x;
    int m0 = blockIdx.y * 128;
    int n0 = blockIdx.x * 128;
    int lane = tid & 31, warp = tid >> 5;
    int wm = warp & 1, wn = warp >> 1;
    int r = lane >> 2, tg = lane & 3;

    uint32_t gsmu = (uint32_t)__cvta_generic_to_shared(gsm);
    const uint32_t stageB = GEMM_STAGE * 2;

    uint32_t laneA = (uint32_t)(((lane & 15) * 40 + ((lane >> 4) << 3)) << 1);
    int bnn = wn * 64 + ((lane >> 4) & 1) * 8 + (lane & 7);
    uint32_t laneB = (uint32_t)((bnn * 40 + ((lane >> 3) & 1) * 8) << 1);

    float acc[4][8][4] = {};
    constexpr int KT = K / 32;

    auto load_stage = [&](int st, int kt) {
        uint32_t base = gsmu + st * stageB;
#pragma unroll
        for (int i = 0; i < 4; i++) {       // A: 128x32 -> 512 chunks / 128 thr
            int chunk = tid + i * 128;
            int row = chunk >> 2, c4 = chunk & 3;
            cp16(base + (uint32_t)((row * 40 + c4 * 8) * 2),
                 A + (size_t)(m0 + row) * K + kt * 32 + c4 * 8);
        }
#pragma unroll
        for (int i = 0; i < 4; i++) {       // B: 128x32
            int chunk = tid + i * 128;
            int row = chunk >> 2, c4 = chunk & 3;
            cp16(base + (uint32_t)(128 * 80) + (uint32_t)((row * 40 + c4 * 8) * 2),
                 W + (size_t)(n0 + row) * K + kt * 32 + c4 * 8);
        }
        cp_commit();
    };

    auto consume = [&](int st) {
        uint32_t abase = gsmu + st * stageB;
        uint32_t bbase = abase + (uint32_t)(128 * 80);
#pragma unroll
        for (int kk = 0; kk < 2; kk++) {
            uint32_t kko = (uint32_t)(kk * 32);
            uint32_t a[4][4];
#pragma unroll
            for (int mt = 0; mt < 4; mt++) {
                uint32_t addr = abase + (uint32_t)(((wm * 64 + mt * 16) * 40) << 1) + laneA + kko;
                ldsm4(a[mt][0], a[mt][1], a[mt][2], a[mt][3], addr);
            }
            uint32_t p[4][4];
#pragma unroll
            for (int q = 0; q < 4; q++)
                ldsm4(p[q][0], p[q][1], p[q][2], p[q][3],
                      bbase + laneB + (uint32_t)(q * 16 * 80) + kko);
#pragma unroll
            for (int mt = 0; mt < 4; mt++)
#pragma unroll
                for (int q = 0; q < 4; q++) {
                    mma16816(acc[mt][2 * q],     a[mt], p[q][0], p[q][1]);
                    mma16816(acc[mt][2 * q + 1], a[mt], p[q][2], p[q][3]);
                }
        }
    };

    load_stage(0, 0);
    load_stage(1, 1);
    load_stage(2, 2);

    int st = 0;
#pragma unroll 1
    for (int kt = 0; kt < KT - 3; kt++) {
        asm volatile("cp.async.wait_group 2;");
        __syncthreads();
        load_stage((st + 3) & 3, kt + 3);
        consume(st);
        st = (st + 1) & 3;
    }
    asm volatile("cp.async.wait_group 2;");
    __syncthreads();
    consume(st); st = (st + 1) & 3;
    asm volatile("cp.async.wait_group 1;");
    __syncthreads();
    consume(st); st = (st + 1) & 3;
    asm volatile("cp.async.wait_group 0;");
    __syncthreads();
    consume(st);

    // epilogue: bias add, stage in smem (stride 136 halves, conflict-free),
    // then fully-coalesced uint4 streaming stores.
    __syncthreads();   // stage buffers now free
    __half* sC = gsm;  // [128][136]
#pragma unroll
    for (int mt = 0; mt < 4; mt++)
#pragma unroll
        for (int j = 0; j < 8; j++) {
            int m = wm * 64 + mt * 16 + r;
            int n = wn * 64 + (j >> 1) * 16 + (j & 1) * 8 + tg * 2;
            float b0 = bias[n0 + n], b1 = bias[n0 + n + 1];
            *(__half2*)&sC[m * 136 + n] =
                __floats2half2_rn(acc[mt][j][0] + b0, acc[mt][j][1] + b1);
            *(__half2*)&sC[(m + 8) * 136 + n] =
                __floats2half2_rn(acc[mt][j][2] + b0, acc[mt][j][3] + b1);
        }
    __syncthreads();
#pragma unroll
    for (int i = 0; i < 16; i++) {
        int ch = tid + i * 128;            // 2048 chunks of 16B
        int row = ch >> 4, off = ch & 15;
        uint4 v = *(uint4*)&sC[row * 136 + off * 8];
        *(uint4*)&g_xg[(size_t)(m0 + row) * GG + n0 + off * 8] = v;
    }
}

// ---------------- persistent LSTM recurrence ----------------
// 128 CTAs = 8 groups x 16 slices, 256 threads (8 warps, 16 gate cols/warp).
// CTA (g,c): batch rows [g*16,g*16+16), hidden [c*32,c*32+32), permuted gate
// cols [c*128,c*128+128). W_hh fragments in REGISTERS (128/thread).
// Register-resident activations via shfl.xor(1) pair exchange (no gate smem).
// Publish: activations write sH; one sync; 64 writers stream uint4 -> g_hbuf,
// bar.sync(1,64), tid0 releases. NO tail sync — warps 2..7 start the next
// step's poll while writers drain (top-of-step sync is the rendezvous).
// LAYER 0: input projection fused, x tile double-buffered (cp.async).
// LAYER 1: xg precomputed by k_gemm_xg; loads issued at step top.
constexpr int LSTM_SMEM0 = (128 * 264 + 128 * 520) * 2;  // 200704 B
constexpr int LSTM_SMEM1 = 128 * 520 * 2;                // 133120 B

template <int LAYER>
__global__ __launch_bounds__(256, 1) void k_lstm() {
    extern __shared__ __half smem[];
    __half* sWx = smem;                                        // layer0 only [128][264]
    __half* R   = (LAYER == 0) ? smem + 128 * 264 : smem;      // staging region
    __half* sW  = R;                                           // [128][520] init only
    __half* sA  = R;                                           // [16][520] (after init)
    __half* sX  = R + 16 * 520;                                // [2][16][264] layer0
    __half* sH  = R + 16 * 520 + 2 * 16 * 264;                 // [16][32]

    const __half* __restrict__ Whh = LAYER ? g_whh1p : g_whh0p;

    int tid = threadIdx.x;
    int lane = tid & 31, warp = tid >> 5;
    int grp = blockIdx.x >> 4;
    int c = blockIdx.x & 15;
    int r = lane >> 2, tg = lane & 3;
    int odd = tg & 1;
    int rowa = odd ? r + 8 : r;            // activation row this lane owns

    // stage W_hh slice rows [c*128, +128) into R
    {
        const uint4* src = (const uint4*)(Whh + (size_t)c * 128 * 512);
#pragma unroll
        for (int i = 0; i < 32; i++) {
            int u = tid + i * 256;
            int row = u >> 6, c4 = u & 63;
            ((uint4*)sW)[row * 65 + c4] = src[u];
        }
    }
    // layer0: load W_ih slice rows [c*128, +128) x 256 into sWx (stride 264)
    if (LAYER == 0) {
        const uint4* src = (const uint4*)(g_wih0p + (size_t)c * 128 * 256);
#pragma unroll
        for (int i = 0; i < 16; i++) {
            int u = tid + i * 256;
            int row = u >> 5, c4 = u & 31;
            *(uint4*)&sWx[row * 264 + c4 * 8] = src[u];
        }
    }
    __syncthreads();

    uint32_t R_u   = (uint32_t)__cvta_generic_to_shared(R);
    uint32_t sX_u  = (uint32_t)__cvta_generic_to_shared(sX);
    uint32_t sWx_u = (uint32_t)__cvta_generic_to_shared(sWx);
    uint32_t aAddr  = R_u  + (uint32_t)((((lane & 15) * 520) + ((lane >> 4) << 3)) << 1);
    uint32_t aAddrX = sX_u + (uint32_t)((((lane & 15) * 264) + ((lane >> 4) << 3)) << 1);
    const uint32_t xBufB = 16 * 264 * 2;   // bytes per sX buffer

    int bn = warp * 16 + ((lane >> 4) & 1) * 8 + (lane & 7);
    uint32_t bAddrX = sWx_u + (uint32_t)(((bn * 264) + ((lane >> 3) & 1) * 8) << 1);

    // preload ALL W_hh fragments into registers (warp owns 16 gate cols, K=512)
    uint32_t wf[32][4];
    {
        uint32_t sW_u = (uint32_t)__cvta_generic_to_shared(sW);
        uint32_t bAddr = sW_u + (uint32_t)(((bn * 520) + ((lane >> 3) & 1) * 8) << 1);
#pragma unroll
        for (int kt = 0; kt < 32; kt++)
            ldsm4(wf[kt][0], wf[kt][1], wf[kt][2], wf[kt][3], bAddr + (uint32_t)(kt * 32));
    }
    __syncthreads();   // frags read; R region may now be reused as sA/sX/sH

    // hidden units this lane owns (per nt) and their biases
    int uu[2];
    float4 b4[2];
#pragma unroll
    for (int nt = 0; nt < 2; nt++) {
        uu[nt] = warp * 4 + nt * 2 + (tg >> 1);
        if (LAYER == 0) b4[nt] = *(const float4*)&g_bias0[c * 128 + uu[nt] * 4];
        else            b4[nt] = make_float4(0.f, 0.f, 0.f, 0.f);
    }

    // x prefetch (layer0): 8 KB tile, 2 chunks/thread
    auto prefetch_x = [&](int t) {
        uint32_t dst = sX_u + (uint32_t)((t & 1)) * xBufB;
#pragma unroll
        for (int i = 0; i < 2; i++) {
            int u = tid + i * 256;
            int row = u >> 5, c4 = u & 31;
            cp16(dst + (uint32_t)((row * 264 + c4 * 8) * 2),
                 g_x16 + ((size_t)(grp * BSUB + row) * TT + t) * EE + c4 * 8);
        }
        cp_commit();
    };
    if (LAYER == 0) prefetch_x(0);

    float cs[2] = {0.f, 0.f};
    int* myflag = &g_flag[(grp * NSLICE + c) * 32];
    int p0 = 2 * warp, p1 = 2 * warp + 1;
    int* f0 = &g_flag[(grp * NSLICE + p0) * 32];
    int* f1 = &g_flag[(grp * NSLICE + p1) * 32];

    for (int t = 0; t < TT; t++) {
        float acc[2][4] = {};
        uint2 xgv[2];

        if (LAYER == 1) {
            // issue xg loads early (independent; overlap with poll + peer ldcv)
            int bgl = grp * BSUB + rowa;
#pragma unroll
            for (int nt = 0; nt < 2; nt++) {
                const __half* xp = g_xg + ((size_t)bgl * TT + t) * GG + c * 128 + uu[nt] * 4;
                xgv[nt] = __ldcs((const uint2*)xp);
            }
        }

        // 1) poll my 2 peers (flag >= t means they published h[t]); t=0 free
        if (t > 0) {
            int v0, v1;
            do {
                asm volatile("ld.acquire.gpu.global.s32 %0, [%1];" : "=r"(v0) : "l"(f0) : "memory");
                asm volatile("ld.acquire.gpu.global.s32 %0, [%1];" : "=r"(v1) : "l"(f1) : "memory");
            } while (v0 < t || v1 < t);
        }
        // 2) issue peer h loads into registers (latency overlapped by x-GEMM)
        uint4 hv0[2], hv1[2];
        {
            int par = t & 1;
            const uint4* s0 = (const uint4*)&g_hbuf[(((size_t)par * NGROUP + grp) * NSLICE + p0) * 512];
            const uint4* s1 = (const uint4*)&g_hbuf[(((size_t)par * NGROUP + grp) * NSLICE + p1) * 512];
#pragma unroll
            for (int j = 0; j < 2; j++) {
                hv0[j] = __ldcv(s0 + lane + j * 32);
                hv1[j] = __ldcv(s1 + lane + j * 32);
            }
        }

        if (LAYER == 0) {
            // 3) consume sX[t&1] (prefetched one step ago); x-GEMM overlaps ldcv
            asm volatile("cp.async.wait_group 0;");
            __syncthreads();
            uint32_t aX = aAddrX + (uint32_t)(t & 1) * xBufB;
#pragma unroll
            for (int kt = 0; kt < 16; kt++) {
                uint32_t ko = (uint32_t)(kt * 32);
                uint32_t a[4], w0, w1, w2, w3;
                ldsm4(a[0], a[1], a[2], a[3], aX + ko);
                ldsm4(w0, w1, w2, w3, bAddrX + ko);
                mma16816(acc[0], a, w0, w1);
                mma16816(acc[1], a, w2, w3);
            }
            if (t + 1 < TT) prefetch_x(t + 1);
        }

        // 4) store peer h into sA
#pragma unroll
        for (int j = 0; j < 2; j++) {
            int chunk = lane + j * 32;
            int row = chunk >> 2, c4 = chunk & 3;
            *(uint4*)&sA[row * 520 + p0 * 32 + c4 * 8] = hv0[j];
            *(uint4*)&sA[row * 520 + p1 * 32 + c4 * 8] = hv1[j];
        }
        __syncthreads();   // rendezvous: also orders prior step's publish reads

        // 5) h-GEMM: gates += h_prev[16x512] @ Wslice^T (W frags in regs)
#pragma unroll
        for (int kt = 0; kt < 32; kt++) {
            uint32_t a[4];
            ldsm4(a[0], a[1], a[2], a[3], aAddr + (uint32_t)(kt * 32));
            mma16816(acc[0], a, wf[kt][0], wf[kt][1]);
            mma16816(acc[1], a, wf[kt][2], wf[kt][3]);
        }

        // 6) register-resident activations: pair-exchange via shfl.xor(1).
#pragma unroll
        for (int nt = 0; nt < 2; nt++) {
            float s0 = __shfl_xor_sync(0xffffffffu, odd ? acc[nt][0] : acc[nt][2], 1);
            float s1 = __shfl_xor_sync(0xffffffffu, odd ? acc[nt][1] : acc[nt][3], 1);
            float ip, fp, gp, op;
            if (odd) { ip = s0;         fp = s1;         gp = acc[nt][2]; op = acc[nt][3]; }
            else     { ip = acc[nt][0]; fp = acc[nt][1]; gp = s0;         op = s1;         }
            if (LAYER == 0) {
                ip += b4[nt].x; fp += b4[nt].y; gp += b4[nt].z; op += b4[nt].w;
            } else {
                __half2 x01 = *(__half2*)&xgv[nt].x;
                __half2 x23 = *(__half2*)&xgv[nt].y;
                ip += __low2float(x01);  fp += __high2float(x01);
                gp += __low2float(x23);  op += __high2float(x23);
            }
            float ig = sigm(ip), fg = sigm(fp), gvv = tanhfast(gp), og = sigm(op);
            float cv = fg * cs[nt] + ig * gvv;
            cs[nt] = cv;
            float hv = og * tanhfast(cv);
            sH[rowa * 32 + uu[nt]] = __float2half(hv);
        }
        __syncthreads();   // all sH writes visible to the 64 writers

        // 7) coalesced publish (64 writers) + release. NO tail sync: warps 2..7
        //    proceed to next step's poll; top-of-step sync is the rendezvous.
        if (tid < 64) {
            int row = tid >> 2, c4 = tid & 3;
            uint4 hv4 = *(uint4*)&sH[row * 32 + c4 * 8];
            int par = (t + 1) & 1;
            *(uint4*)&g_hbuf[(((size_t)par * NGROUP + grp) * NSLICE + c) * 512
                             + row * 32 + c4 * 8] = hv4;
            asm volatile("bar.sync 1, 64;");
            if (tid == 0)
                asm volatile("st.release.gpu.global.s32 [%0], %1;"
                             :: "l"(myflag), "r"(t + 1) : "memory");
            int bgl = grp * BSUB + row;
            if (LAYER == 0)
                __stcs((uint4*)&g_h1[((size_t)bgl * TT + t) * HH + c * 32 + c4 * 8], hv4);
            if (LAYER == 1 && t == TT - 1) {
                const __half* hp = &sH[row * 32 + c4 * 8];
                float* dp = &g_hlast[bgl * HH + c * 32 + c4 * 8];
#pragma unroll
                for (int e = 0; e < 8; e++) dp[e] = __half2float(hp[e]);
            }
        }
    }
}

// ---------------- final FC + sigmoid ----------------
__global__ void k_fc(const float* __restrict__ wfc, const float* __restrict__ bfc,
                     float* __restrict__ out) {
    int w = blockIdx.x * 4 + (threadIdx.x >> 5);
    int lane = threadIdx.x & 31;
    if (w < BB) {
        float s = 0.f;
        for (int k = lane; k < HH; k += 32) s += g_hlast[w * HH + k] * wfc[k];
#pragma unroll
        for (int o = 16; o; o >>= 1) s += __shfl_xor_sync(0xffffffffu, s, o);
        if (lane == 0) out[w] = 1.f / (1.f + __expf(-(s + bfc[0])));
    }
}

// ---------------- launch ----------------
extern "C" void kernel_launch(void* const* d_in, const int* in_sizes, int n_in,
                              void* d_out, int out_size) {
    const float* x    = (const float*)d_in[0];
    const float* wih0 = (const float*)d_in[1];
    const float* whh0 = (const float*)d_in[2];
    const float* bih0 = (const float*)d_in[3];
    const float* bhh0 = (const float*)d_in[4];
    const float* wih1 = (const float*)d_in[5];
    const float* whh1 = (const float*)d_in[6];
    const float* bih1 = (const float*)d_in[7];
    const float* bhh1 = (const float*)d_in[8];
    const float* wfc  = (const float*)d_in[9];
    const float* bfc  = (const float*)d_in[10];
    float* out = (float*)d_out;

    cudaFuncSetAttribute(k_lstm<0>, cudaFuncAttributeMaxDynamicSharedMemorySize, LSTM_SMEM0);
    cudaFuncSetAttribute(k_lstm<1>, cudaFuncAttributeMaxDynamicSharedMemorySize, LSTM_SMEM1);
    cudaFuncSetAttribute(k_gemm_xg<HH>, cudaFuncAttributeMaxDynamicSharedMemorySize, GEMM_SMEM);

    // prep: fp16 conversions + gate-column permutation
    k_conv_x<<<(MR * EE + 255) / 256, 256>>>(x);
    k_prep_w<<<dim3((GG * HH + 255) / 256, 4), 256>>>(wih0, whh0, wih1, whh1);
    k_prep_b<<<dim3((GG + 255) / 256, 2), 256>>>(bih0, bhh0, bih1, bhh1);

    // layer 1 (input projection fused, x double-buffered)
    k_reset<<<256, 256>>>();
    k_lstm<0><<<NGROUP * NSLICE, 256, LSTM_SMEM0>>>();

    // layer 2
    k_gemm_xg<HH><<<dim3(GG / 128, MR / 128), 128, GEMM_SMEM>>>();
    k_reset<<<256, 256>>>();
    k_lstm<1><<<NGROUP * NSLICE, 256, LSTM_SMEM1>>>();

    // head
    k_fc<<<(BB + 3) / 4, 128>>>(wfc, bfc, out);
}